// round 1
// baseline (speedup 1.0000x reference)
#include <cuda_runtime.h>

#define DMODEL 768
#define NH     12
#define DH     64
#define WIN    16
#define WW     32
#define NWIN   128
#define BB     2
#define TT     2048
#define IGNORE_V (-1.0e6f)

// Scratch (device globals: allocation-free)
__device__ float g_abcde[(size_t)BB * TT * 5 * NH * DH]; // (B,T,5*H*D) = 62.9 MB
__device__ float g_z[(size_t)BB * TT * NH * DH];         // (B,T,H*D)   = 12.6 MB

// ---------------------------------------------------------------------------
// SGEMM: C(MxN) = A(MxK) @ B(KxN) + bias(N).  128x128 block, 8x8/thread, BK=16.
// Requires M%128==0, N%128==0, K%16==0 (true for all shapes here).
// ---------------------------------------------------------------------------
__global__ __launch_bounds__(256)
void sgemm_bias(const float* __restrict__ A, const float* __restrict__ B,
                const float* __restrict__ bias, float* __restrict__ C,
                int M, int N, int K)
{
    __shared__ float As[16][128];
    __shared__ float Bs[16][128];

    const int tid   = threadIdx.x;
    const int crow0 = blockIdx.y * 128;
    const int ccol0 = blockIdx.x * 128;

    const int tx = tid & 15;   // 0..15 -> col group
    const int ty = tid >> 4;   // 0..15 -> row group

    float acc[8][8];
#pragma unroll
    for (int i = 0; i < 8; i++)
#pragma unroll
        for (int j = 0; j < 8; j++) acc[i][j] = 0.0f;

    const int arow = tid >> 2;         // 0..63
    const int acol = (tid & 3) << 2;   // 0,4,8,12
    const int brow = tid >> 5;         // 0..7
    const int bcol = (tid & 31) << 2;  // 0..124

    const float* Ag = A + (size_t)crow0 * K;
    const float* Bg = B + ccol0;

    for (int k0 = 0; k0 < K; k0 += 16) {
#pragma unroll
        for (int r = 0; r < 2; r++) {
            int row = arow + r * 64;
            float4 v = *(const float4*)(Ag + (size_t)row * K + k0 + acol);
            As[acol + 0][row] = v.x;
            As[acol + 1][row] = v.y;
            As[acol + 2][row] = v.z;
            As[acol + 3][row] = v.w;
        }
#pragma unroll
        for (int r = 0; r < 2; r++) {
            int row = brow + r * 8;
            float4 v = *(const float4*)(Bg + (size_t)(k0 + row) * N + bcol);
            *(float4*)&Bs[row][bcol] = v;
        }
        __syncthreads();

#pragma unroll
        for (int k = 0; k < 16; k++) {
            float ar[8], br[8];
            *(float4*)&ar[0] = *(const float4*)&As[k][ty * 8];
            *(float4*)&ar[4] = *(const float4*)&As[k][ty * 8 + 4];
            *(float4*)&br[0] = *(const float4*)&Bs[k][tx * 8];
            *(float4*)&br[4] = *(const float4*)&Bs[k][tx * 8 + 4];
#pragma unroll
            for (int i = 0; i < 8; i++)
#pragma unroll
                for (int j = 0; j < 8; j++)
                    acc[i][j] += ar[i] * br[j];
        }
        __syncthreads();
    }

#pragma unroll
    for (int i = 0; i < 8; i++) {
        int row = crow0 + ty * 8 + i;
#pragma unroll
        for (int j = 0; j < 8; j += 4) {
            int col = ccol0 + tx * 8 + j;
            float4 o;
            o.x = acc[i][j + 0] + bias[col + 0];
            o.y = acc[i][j + 1] + bias[col + 1];
            o.z = acc[i][j + 2] + bias[col + 2];
            o.w = acc[i][j + 3] + bias[col + 3];
            *(float4*)&C[(size_t)row * N + col] = o;
        }
    }
}

// ---------------------------------------------------------------------------
// Local trittention core. One block per (bh, window n): 512 threads = 16 warps,
// warp q handles query position q; lane = m owns score row m (over l).
// ---------------------------------------------------------------------------
#define SPAD 68  // 64 + 4 pad: row-major lane reads drop to 4-way conflicts

__global__ __launch_bounds__(512)
void attn_kernel()
{
    __shared__ float sa[32][SPAD];
    __shared__ float sb[32][SPAD];
    __shared__ float sd[32][SPAD];
    __shared__ float se[32][SPAD];
    __shared__ float sc[16][SPAD];

    const int blk = blockIdx.x;
    const int n   = blk & (NWIN - 1);
    const int bh  = blk >> 7;          // NWIN = 128
    const int b   = bh / NH;
    const int h   = bh % NH;
    const int tid = threadIdx.x;

    // ---- stage a_l, b_l, d_l, e_l (32x64 each) and c (16x64) ----
    {
        int m  = tid >> 4;          // 0..31
        int c4 = (tid & 15) << 2;   // 0..60
        int t  = n * WIN + m - WIN; // global token of look-around row m
        float4 z4 = make_float4(0.f, 0.f, 0.f, 0.f);
        float4 va = z4, vb = z4, vd = z4, ve = z4;
        if (t >= 0) {
            const float* base = g_abcde + ((size_t)(b * TT + t)) * (5 * DMODEL)
                              + h * DH + c4;
            va = *(const float4*)(base + 0 * DMODEL);
            vb = *(const float4*)(base + 1 * DMODEL);
            vd = *(const float4*)(base + 3 * DMODEL);
            ve = *(const float4*)(base + 4 * DMODEL);
        }
        *(float4*)&sa[m][c4] = va;
        *(float4*)&sb[m][c4] = vb;
        *(float4*)&sd[m][c4] = vd;
        *(float4*)&se[m][c4] = ve;
        if (tid < 256) {
            int w  = tid >> 4;
            int cc = (tid & 15) << 2;
            int tq = n * WIN + w;
            const float* base = g_abcde + ((size_t)(b * TT + tq)) * (5 * DMODEL)
                              + 2 * DMODEL + h * DH + cc;
            *(float4*)&sc[w][cc] = *(const float4*)base;
        }
    }
    __syncthreads();

    const int q    = tid >> 5;   // warp id = query position in window
    const int lane = tid & 31;   // = m (score row)

    // P[d] = a_l[m,d] * c[q,d]
    float P[64];
#pragma unroll
    for (int d = 0; d < 64; d++) P[d] = sa[lane][d] * sc[q][d];

    const int qg  = n * WIN + q;
    const int bbm = (lane < WIN) ? ((n == 0) ? 0 : (n - 1) * WIN + lane)
                                 : (n * WIN + lane - WIN);

    // scores row m over l, with mask + zero->IGNORE + /D_HEAD
    float val[32];
#pragma unroll
    for (int l = 0; l < 32; l++) {
        float s = 0.0f;
        const float4* bp = (const float4*)&sb[l][0];
#pragma unroll
        for (int j = 0; j < 16; j++) {
            float4 v = bp[j];
            s += P[4 * j + 0] * v.x;
            s += P[4 * j + 1] * v.y;
            s += P[4 * j + 2] * v.z;
            s += P[4 * j + 3] * v.w;
        }
        int bbl = (l < WIN) ? ((n == 0) ? 0 : (n - 1) * WIN + l)
                            : (n * WIN + l - WIN);
        if ((qg < bbl) || (bbl <= bbm) || (s == 0.0f)) s = IGNORE_V;
        val[l] = s * (1.0f / 64.0f);
    }

    // softmax over the full 32x32 (warp = m axis, regs = l axis)
    float mx = val[0];
#pragma unroll
    for (int l = 1; l < 32; l++) mx = fmaxf(mx, val[l]);
#pragma unroll
    for (int off = 16; off; off >>= 1)
        mx = fmaxf(mx, __shfl_xor_sync(0xffffffffu, mx, off));

    float sum = 0.0f;
#pragma unroll
    for (int l = 0; l < 32; l++) {
        float e = __expf(val[l] - mx);
        val[l] = e;
        sum += e;
    }
#pragma unroll
    for (int off = 16; off; off >>= 1)
        sum += __shfl_xor_sync(0xffffffffu, sum, off);

    const float inv = 1.0f / sum;
    float pm = 0.0f;                  // row marginal: sum_l p[m,l]  (lane=m)
#pragma unroll
    for (int l = 0; l < 32; l++) { val[l] *= inv; pm += val[l]; }

    float pl_own = 0.0f;              // col marginal: lane l ends owning sum_m p[m,l]
#pragma unroll
    for (int l = 0; l < 32; l++) {
        float v = val[l];
#pragma unroll
        for (int off = 16; off; off >>= 1)
            v += __shfl_xor_sync(0xffffffffu, v, off);
        if (lane == l) pl_own = v;
    }

    // z[d] = sum_m pm[m]*d_l[m,d] + sum_l pl[l]*e_l[l,d]; lane covers d and d+32
    float acc0 = 0.0f, acc1 = 0.0f;
#pragma unroll 1
    for (int m = 0; m < 32; m++) {
        float pmv = __shfl_sync(0xffffffffu, pm, m);
        float plv = __shfl_sync(0xffffffffu, pl_own, m);
        acc0 += pmv * sd[m][lane]      + plv * se[m][lane];
        acc1 += pmv * sd[m][lane + 32] + plv * se[m][lane + 32];
    }

    float* zrow = g_z + ((size_t)(b * TT + qg)) * (NH * DH) + h * DH;
    zrow[lane]      = acc0;
    zrow[lane + 32] = acc1;
}

// ---------------------------------------------------------------------------
extern "C" void kernel_launch(void* const* d_in, const int* in_sizes, int n_in,
                              void* d_out, int out_size)
{
    const float* x  = (const float*)d_in[0];  // (2,2048,768)
    const float* W1 = (const float*)d_in[1];  // (768, 3840)
    const float* b1 = (const float*)d_in[2];  // (3840)
    const float* WO = (const float*)d_in[3];  // (768, 768)
    const float* bO = (const float*)d_in[4];  // (768)
    float* out = (float*)d_out;               // (2,2048,768)

    float* abcde = nullptr;
    float* zbuf  = nullptr;
    cudaGetSymbolAddress((void**)&abcde, g_abcde);
    cudaGetSymbolAddress((void**)&zbuf,  g_z);

    const int M = BB * TT;          // 4096

    // 1) abcde = x @ W_abcde + b_abcde
    sgemm_bias<<<dim3((5 * NH * DH) / 128, M / 128), 256>>>(
        x, W1, b1, abcde, M, 5 * NH * DH, DMODEL);

    // 2) local trittention -> z
    attn_kernel<<<BB * NH * NWIN, 512>>>();

    // 3) out = z @ W_O + b_O
    sgemm_bias<<<dim3(DMODEL / 128, M / 128), 256>>>(
        zbuf, WO, bO, out, M, DMODEL, NH * DH);
}

// round 2
// speedup vs baseline: 2.0054x; 2.0054x over previous
#include <cuda_runtime.h>

#define DMODEL 768
#define NH     12
#define DH     64
#define WIN    16
#define WW     32
#define NWIN   128
#define BB     2
#define TT     2048
#define IGNORE_V (-1.0e6f)

// Scratch (device globals: allocation-free)
__device__ float g_abcde[(size_t)BB * TT * 5 * NH * DH]; // (B,T,5*H*D) = 62.9 MB
__device__ float g_z[(size_t)BB * TT * NH * DH];         // (B,T,H*D)   = 12.6 MB

// ---------------------------------------------------------------------------
// TF32 tensor-core GEMM: C(MxN) = A(MxK) @ B(KxN) + bias(N)
// Block 128x128, BK=16, 8 warps (2x4), warp tile 64x32, mma.m16n8k8.tf32.
// Conversion fp32->tf32 (round-to-nearest) happens once at staging time.
// Requires M%128==0, N%128==0, K%16==0.
// ---------------------------------------------------------------------------
#define BM 128
#define BN 128
#define BK 16
#define ASTR 20    // As row stride (floats): 20g+t covers all 32 banks
#define BSTR 136   // Bs row stride (floats): 8t+g covers all 32 banks

__device__ __forceinline__ unsigned f2tf32(float x) {
    unsigned r;
    asm("cvt.rna.tf32.f32 %0, %1;" : "=r"(r) : "f"(x));
    return r;
}

__device__ __forceinline__ void mma_tf32(float c[4], const unsigned a[4], const unsigned b[2]) {
    asm volatile(
        "mma.sync.aligned.m16n8k8.row.col.f32.tf32.tf32.f32 "
        "{%0,%1,%2,%3}, {%4,%5,%6,%7}, {%8,%9}, {%0,%1,%2,%3};"
        : "+f"(c[0]), "+f"(c[1]), "+f"(c[2]), "+f"(c[3])
        : "r"(a[0]), "r"(a[1]), "r"(a[2]), "r"(a[3]), "r"(b[0]), "r"(b[1]));
}

__global__ __launch_bounds__(256)
void gemm_tf32(const float* __restrict__ A, const float* __restrict__ B,
               const float* __restrict__ bias, float* __restrict__ C,
               int M, int N, int K)
{
    __shared__ unsigned As[2][BM][ASTR];
    __shared__ unsigned Bs[2][BK][BSTR];

    const int tid   = threadIdx.x;
    const int lane  = tid & 31;
    const int wid   = tid >> 5;
    const int g     = lane >> 2;   // group id (0..7)
    const int t     = lane & 3;    // thread-in-group (0..3)
    const int wm    = wid & 1;     // warp row (0..1) -> 64 rows
    const int wn    = wid >> 1;    // warp col (0..3) -> 32 cols

    const int crow0 = blockIdx.y * BM;
    const int ccol0 = blockIdx.x * BN;

    float acc[4][4][4];
#pragma unroll
    for (int mt = 0; mt < 4; mt++)
#pragma unroll
        for (int nt = 0; nt < 4; nt++)
#pragma unroll
            for (int i = 0; i < 4; i++) acc[mt][nt][i] = 0.0f;

    // staging addresses
    const int ar  = tid >> 2;          // 0..63 (A rows, +64 for second)
    const int ac  = (tid & 3) << 2;    // 0,4,8,12
    const int br  = tid >> 5;          // 0..7  (B rows, +8 for second)
    const int bc  = (tid & 31) << 2;   // 0..124
    const float* Ag = A + (size_t)(crow0 + ar) * K + ac;
    const float* Bg = B + (size_t)br * N + ccol0 + bc;

    float4 ra0, ra1, rb0, rb1;

    // prologue: tile 0
    ra0 = *(const float4*)(Ag);
    ra1 = *(const float4*)(Ag + (size_t)64 * K);
    rb0 = *(const float4*)(Bg);
    rb1 = *(const float4*)(Bg + (size_t)8 * N);
    {
        As[0][ar][ac + 0] = f2tf32(ra0.x); As[0][ar][ac + 1] = f2tf32(ra0.y);
        As[0][ar][ac + 2] = f2tf32(ra0.z); As[0][ar][ac + 3] = f2tf32(ra0.w);
        As[0][ar + 64][ac + 0] = f2tf32(ra1.x); As[0][ar + 64][ac + 1] = f2tf32(ra1.y);
        As[0][ar + 64][ac + 2] = f2tf32(ra1.z); As[0][ar + 64][ac + 3] = f2tf32(ra1.w);
        Bs[0][br][bc + 0] = f2tf32(rb0.x); Bs[0][br][bc + 1] = f2tf32(rb0.y);
        Bs[0][br][bc + 2] = f2tf32(rb0.z); Bs[0][br][bc + 3] = f2tf32(rb0.w);
        Bs[0][br + 8][bc + 0] = f2tf32(rb1.x); Bs[0][br + 8][bc + 1] = f2tf32(rb1.y);
        Bs[0][br + 8][bc + 2] = f2tf32(rb1.z); Bs[0][br + 8][bc + 3] = f2tf32(rb1.w);
    }
    __syncthreads();

    int buf = 0;
    for (int k0 = BK; k0 <= K; k0 += BK) {
        const bool has_next = (k0 < K);
        if (has_next) {
            ra0 = *(const float4*)(Ag + k0);
            ra1 = *(const float4*)(Ag + (size_t)64 * K + k0);
            rb0 = *(const float4*)(Bg + (size_t)k0 * N);
            rb1 = *(const float4*)(Bg + (size_t)(k0 + 8) * N);
        }

        // compute on buf
#pragma unroll
        for (int ks = 0; ks < 2; ks++) {
            const int kk = ks * 8;
            unsigned af[4][4], bf[4][2];
#pragma unroll
            for (int mt = 0; mt < 4; mt++) {
                const int m0 = wm * 64 + mt * 16;
                af[mt][0] = As[buf][m0 + g][kk + t];
                af[mt][1] = As[buf][m0 + g + 8][kk + t];
                af[mt][2] = As[buf][m0 + g][kk + t + 4];
                af[mt][3] = As[buf][m0 + g + 8][kk + t + 4];
            }
#pragma unroll
            for (int nt = 0; nt < 4; nt++) {
                const int n0 = wn * 32 + nt * 8;
                bf[nt][0] = Bs[buf][kk + t][n0 + g];
                bf[nt][1] = Bs[buf][kk + t + 4][n0 + g];
            }
#pragma unroll
            for (int mt = 0; mt < 4; mt++)
#pragma unroll
                for (int nt = 0; nt < 4; nt++)
                    mma_tf32(acc[mt][nt], af[mt], bf[nt]);
        }

        if (has_next) {
            const int nb = buf ^ 1;
            As[nb][ar][ac + 0] = f2tf32(ra0.x); As[nb][ar][ac + 1] = f2tf32(ra0.y);
            As[nb][ar][ac + 2] = f2tf32(ra0.z); As[nb][ar][ac + 3] = f2tf32(ra0.w);
            As[nb][ar + 64][ac + 0] = f2tf32(ra1.x); As[nb][ar + 64][ac + 1] = f2tf32(ra1.y);
            As[nb][ar + 64][ac + 2] = f2tf32(ra1.z); As[nb][ar + 64][ac + 3] = f2tf32(ra1.w);
            Bs[nb][br][bc + 0] = f2tf32(rb0.x); Bs[nb][br][bc + 1] = f2tf32(rb0.y);
            Bs[nb][br][bc + 2] = f2tf32(rb0.z); Bs[nb][br][bc + 3] = f2tf32(rb0.w);
            Bs[nb][br + 8][bc + 0] = f2tf32(rb1.x); Bs[nb][br + 8][bc + 1] = f2tf32(rb1.y);
            Bs[nb][br + 8][bc + 2] = f2tf32(rb1.z); Bs[nb][br + 8][bc + 3] = f2tf32(rb1.w);
            __syncthreads();
            buf = nb;
        }
    }

    // epilogue: C fragment (c0,c1) at (row, 2t), (c2,c3) at (row+8, 2t)
#pragma unroll
    for (int mt = 0; mt < 4; mt++) {
        const int row = crow0 + wm * 64 + mt * 16 + g;
#pragma unroll
        for (int nt = 0; nt < 4; nt++) {
            const int col = ccol0 + wn * 32 + nt * 8 + 2 * t;
            const float2 bv = *(const float2*)&bias[col];
            float2 o0, o1;
            o0.x = acc[mt][nt][0] + bv.x;
            o0.y = acc[mt][nt][1] + bv.y;
            o1.x = acc[mt][nt][2] + bv.x;
            o1.y = acc[mt][nt][3] + bv.y;
            *(float2*)&C[(size_t)row * N + col]       = o0;
            *(float2*)&C[(size_t)(row + 8) * N + col] = o1;
        }
    }
}

// ---------------------------------------------------------------------------
// Local trittention core. One block per (bh, window n): 512 threads = 16 warps,
// warp q handles query position q; lane = m owns score row m (over l).
// ---------------------------------------------------------------------------
#define SPAD 68  // 64 + 4 pad

__global__ __launch_bounds__(512)
void attn_kernel()
{
    __shared__ float sa[32][SPAD];
    __shared__ float sb[32][SPAD];
    __shared__ float sd[32][SPAD];
    __shared__ float se[32][SPAD];
    __shared__ float sc[16][SPAD];

    const int blk = blockIdx.x;
    const int n   = blk & (NWIN - 1);
    const int bh  = blk >> 7;          // NWIN = 128
    const int b   = bh / NH;
    const int h   = bh % NH;
    const int tid = threadIdx.x;

    // ---- stage a_l, b_l, d_l, e_l (32x64 each) and c (16x64) ----
    {
        int m  = tid >> 4;          // 0..31
        int c4 = (tid & 15) << 2;   // 0..60
        int t  = n * WIN + m - WIN; // global token of look-around row m
        float4 z4 = make_float4(0.f, 0.f, 0.f, 0.f);
        float4 va = z4, vb = z4, vd = z4, ve = z4;
        if (t >= 0) {
            const float* base = g_abcde + ((size_t)(b * TT + t)) * (5 * DMODEL)
                              + h * DH + c4;
            va = *(const float4*)(base + 0 * DMODEL);
            vb = *(const float4*)(base + 1 * DMODEL);
            vd = *(const float4*)(base + 3 * DMODEL);
            ve = *(const float4*)(base + 4 * DMODEL);
        }
        *(float4*)&sa[m][c4] = va;
        *(float4*)&sb[m][c4] = vb;
        *(float4*)&sd[m][c4] = vd;
        *(float4*)&se[m][c4] = ve;
        if (tid < 256) {
            int w  = tid >> 4;
            int cc = (tid & 15) << 2;
            int tq = n * WIN + w;
            const float* base = g_abcde + ((size_t)(b * TT + tq)) * (5 * DMODEL)
                              + 2 * DMODEL + h * DH + cc;
            *(float4*)&sc[w][cc] = *(const float4*)base;
        }
    }
    __syncthreads();

    const int q    = tid >> 5;   // warp id = query position in window
    const int lane = tid & 31;   // = m (score row)

    // P[d] = a_l[m,d] * c[q,d]
    float P[64];
#pragma unroll
    for (int d = 0; d < 64; d++) P[d] = sa[lane][d] * sc[q][d];

    const int qg  = n * WIN + q;
    const int bbm = (lane < WIN) ? ((n == 0) ? 0 : (n - 1) * WIN + lane)
                                 : (n * WIN + lane - WIN);

    // scores row m over l, with mask + zero->IGNORE + /D_HEAD
    float val[32];
#pragma unroll
    for (int l = 0; l < 32; l++) {
        float s = 0.0f;
        const float4* bp = (const float4*)&sb[l][0];
#pragma unroll
        for (int j = 0; j < 16; j++) {
            float4 v = bp[j];
            s += P[4 * j + 0] * v.x;
            s += P[4 * j + 1] * v.y;
            s += P[4 * j + 2] * v.z;
            s += P[4 * j + 3] * v.w;
        }
        int bbl = (l < WIN) ? ((n == 0) ? 0 : (n - 1) * WIN + l)
                            : (n * WIN + l - WIN);
        if ((qg < bbl) || (bbl <= bbm) || (s == 0.0f)) s = IGNORE_V;
        val[l] = s * (1.0f / 64.0f);
    }

    // softmax over the full 32x32 (warp = m axis, regs = l axis)
    float mx = val[0];
#pragma unroll
    for (int l = 1; l < 32; l++) mx = fmaxf(mx, val[l]);
#pragma unroll
    for (int off = 16; off; off >>= 1)
        mx = fmaxf(mx, __shfl_xor_sync(0xffffffffu, mx, off));

    float sum = 0.0f;
#pragma unroll
    for (int l = 0; l < 32; l++) {
        float e = __expf(val[l] - mx);
        val[l] = e;
        sum += e;
    }
#pragma unroll
    for (int off = 16; off; off >>= 1)
        sum += __shfl_xor_sync(0xffffffffu, sum, off);

    const float inv = 1.0f / sum;
    float pm = 0.0f;                  // row marginal: sum_l p[m,l]  (lane=m)
#pragma unroll
    for (int l = 0; l < 32; l++) { val[l] *= inv; pm += val[l]; }

    float pl_own = 0.0f;              // col marginal: lane l ends owning sum_m p[m,l]
#pragma unroll
    for (int l = 0; l < 32; l++) {
        float v = val[l];
#pragma unroll
        for (int off = 16; off; off >>= 1)
            v += __shfl_xor_sync(0xffffffffu, v, off);
        if (lane == l) pl_own = v;
    }

    // z[d] = sum_m pm[m]*d_l[m,d] + sum_l pl[l]*e_l[l,d]; lane covers d and d+32
    float acc0 = 0.0f, acc1 = 0.0f;
#pragma unroll 1
    for (int m = 0; m < 32; m++) {
        float pmv = __shfl_sync(0xffffffffu, pm, m);
        float plv = __shfl_sync(0xffffffffu, pl_own, m);
        acc0 += pmv * sd[m][lane]      + plv * se[m][lane];
        acc1 += pmv * sd[m][lane + 32] + plv * se[m][lane + 32];
    }

    float* zrow = g_z + ((size_t)(b * TT + qg)) * (NH * DH) + h * DH;
    zrow[lane]      = acc0;
    zrow[lane + 32] = acc1;
}

// ---------------------------------------------------------------------------
extern "C" void kernel_launch(void* const* d_in, const int* in_sizes, int n_in,
                              void* d_out, int out_size)
{
    const float* x  = (const float*)d_in[0];  // (2,2048,768)
    const float* W1 = (const float*)d_in[1];  // (768, 3840)
    const float* b1 = (const float*)d_in[2];  // (3840)
    const float* WO = (const float*)d_in[3];  // (768, 768)
    const float* bO = (const float*)d_in[4];  // (768)
    float* out = (float*)d_out;               // (2,2048,768)

    float* abcde = nullptr;
    float* zbuf  = nullptr;
    cudaGetSymbolAddress((void**)&abcde, g_abcde);
    cudaGetSymbolAddress((void**)&zbuf,  g_z);

    const int M = BB * TT;          // 4096

    // 1) abcde = x @ W_abcde + b_abcde
    gemm_tf32<<<dim3((5 * NH * DH) / 128, M / 128), 256>>>(
        x, W1, b1, abcde, M, 5 * NH * DH, DMODEL);

    // 2) local trittention -> z
    attn_kernel<<<BB * NH * NWIN, 512>>>();

    // 3) out = z @ W_O + b_O
    gemm_tf32<<<dim3(DMODEL / 128, M / 128), 256>>>(
        zbuf, WO, bO, out, M, DMODEL, NH * DH);
}

// round 3
// speedup vs baseline: 3.0173x; 1.5046x over previous
#include <cuda_runtime.h>

#define DMODEL 768
#define NH     12
#define DH     64
#define WIN    16
#define WW     32
#define NWIN   128
#define BB     2
#define TT     2048
#define IGNORE_V (-1.0e6f)

// Scratch (device globals: allocation-free)
__device__ float g_abcde[(size_t)BB * TT * 5 * NH * DH]; // (B,T,5*H*D) = 62.9 MB
__device__ float g_z[(size_t)BB * TT * NH * DH];         // (B,T,H*D)   = 12.6 MB

__device__ __forceinline__ unsigned f2tf32(float x) {
    unsigned r;
    asm("cvt.rna.tf32.f32 %0, %1;" : "=r"(r) : "f"(x));
    return r;
}

__device__ __forceinline__ void mma_tf32(float c[4], const unsigned a[4], const unsigned b[2]) {
    asm volatile(
        "mma.sync.aligned.m16n8k8.row.col.f32.tf32.tf32.f32 "
        "{%0,%1,%2,%3}, {%4,%5,%6,%7}, {%8,%9}, {%0,%1,%2,%3};"
        : "+f"(c[0]), "+f"(c[1]), "+f"(c[2]), "+f"(c[3])
        : "r"(a[0]), "r"(a[1]), "r"(a[2]), "r"(a[3]), "r"(b[0]), "r"(b[1]));
}

// ---------------------------------------------------------------------------
// TF32 tensor-core GEMM: C(MxN) = A(MxK) @ B(KxN) + bias(N)
// Block 128x128, BK=16, 8 warps (2x4), warp tile 64x32, mma.m16n8k8.tf32.
// ---------------------------------------------------------------------------
#define BM 128
#define BN 128
#define BK 16
#define ASTR 20
#define BSTR 136

__global__ __launch_bounds__(256)
void gemm_tf32(const float* __restrict__ A, const float* __restrict__ B,
               const float* __restrict__ bias, float* __restrict__ C,
               int M, int N, int K)
{
    __shared__ unsigned As[2][BM][ASTR];
    __shared__ unsigned Bs[2][BK][BSTR];

    const int tid   = threadIdx.x;
    const int lane  = tid & 31;
    const int wid   = tid >> 5;
    const int g     = lane >> 2;
    const int t     = lane & 3;
    const int wm    = wid & 1;
    const int wn    = wid >> 1;

    const int crow0 = blockIdx.y * BM;
    const int ccol0 = blockIdx.x * BN;

    float acc[4][4][4];
#pragma unroll
    for (int mt = 0; mt < 4; mt++)
#pragma unroll
        for (int nt = 0; nt < 4; nt++)
#pragma unroll
            for (int i = 0; i < 4; i++) acc[mt][nt][i] = 0.0f;

    const int ar  = tid >> 2;
    const int ac  = (tid & 3) << 2;
    const int br  = tid >> 5;
    const int bc  = (tid & 31) << 2;
    const float* Ag = A + (size_t)(crow0 + ar) * K + ac;
    const float* Bg = B + (size_t)br * N + ccol0 + bc;

    float4 ra0, ra1, rb0, rb1;

    ra0 = *(const float4*)(Ag);
    ra1 = *(const float4*)(Ag + (size_t)64 * K);
    rb0 = *(const float4*)(Bg);
    rb1 = *(const float4*)(Bg + (size_t)8 * N);
    {
        As[0][ar][ac + 0] = f2tf32(ra0.x); As[0][ar][ac + 1] = f2tf32(ra0.y);
        As[0][ar][ac + 2] = f2tf32(ra0.z); As[0][ar][ac + 3] = f2tf32(ra0.w);
        As[0][ar + 64][ac + 0] = f2tf32(ra1.x); As[0][ar + 64][ac + 1] = f2tf32(ra1.y);
        As[0][ar + 64][ac + 2] = f2tf32(ra1.z); As[0][ar + 64][ac + 3] = f2tf32(ra1.w);
        Bs[0][br][bc + 0] = f2tf32(rb0.x); Bs[0][br][bc + 1] = f2tf32(rb0.y);
        Bs[0][br][bc + 2] = f2tf32(rb0.z); Bs[0][br][bc + 3] = f2tf32(rb0.w);
        Bs[0][br + 8][bc + 0] = f2tf32(rb1.x); Bs[0][br + 8][bc + 1] = f2tf32(rb1.y);
        Bs[0][br + 8][bc + 2] = f2tf32(rb1.z); Bs[0][br + 8][bc + 3] = f2tf32(rb1.w);
    }
    __syncthreads();

    int buf = 0;
    for (int k0 = BK; k0 <= K; k0 += BK) {
        const bool has_next = (k0 < K);
        if (has_next) {
            ra0 = *(const float4*)(Ag + k0);
            ra1 = *(const float4*)(Ag + (size_t)64 * K + k0);
            rb0 = *(const float4*)(Bg + (size_t)k0 * N);
            rb1 = *(const float4*)(Bg + (size_t)(k0 + 8) * N);
        }

#pragma unroll
        for (int ks = 0; ks < 2; ks++) {
            const int kk = ks * 8;
            unsigned af[4][4], bf[4][2];
#pragma unroll
            for (int mt = 0; mt < 4; mt++) {
                const int m0 = wm * 64 + mt * 16;
                af[mt][0] = As[buf][m0 + g][kk + t];
                af[mt][1] = As[buf][m0 + g + 8][kk + t];
                af[mt][2] = As[buf][m0 + g][kk + t + 4];
                af[mt][3] = As[buf][m0 + g + 8][kk + t + 4];
            }
#pragma unroll
            for (int nt = 0; nt < 4; nt++) {
                const int n0 = wn * 32 + nt * 8;
                bf[nt][0] = Bs[buf][kk + t][n0 + g];
                bf[nt][1] = Bs[buf][kk + t + 4][n0 + g];
            }
#pragma unroll
            for (int mt = 0; mt < 4; mt++)
#pragma unroll
                for (int nt = 0; nt < 4; nt++)
                    mma_tf32(acc[mt][nt], af[mt], bf[nt]);
        }

        if (has_next) {
            const int nb = buf ^ 1;
            As[nb][ar][ac + 0] = f2tf32(ra0.x); As[nb][ar][ac + 1] = f2tf32(ra0.y);
            As[nb][ar][ac + 2] = f2tf32(ra0.z); As[nb][ar][ac + 3] = f2tf32(ra0.w);
            As[nb][ar + 64][ac + 0] = f2tf32(ra1.x); As[nb][ar + 64][ac + 1] = f2tf32(ra1.y);
            As[nb][ar + 64][ac + 2] = f2tf32(ra1.z); As[nb][ar + 64][ac + 3] = f2tf32(ra1.w);
            Bs[nb][br][bc + 0] = f2tf32(rb0.x); Bs[nb][br][bc + 1] = f2tf32(rb0.y);
            Bs[nb][br][bc + 2] = f2tf32(rb0.z); Bs[nb][br][bc + 3] = f2tf32(rb0.w);
            Bs[nb][br + 8][bc + 0] = f2tf32(rb1.x); Bs[nb][br + 8][bc + 1] = f2tf32(rb1.y);
            Bs[nb][br + 8][bc + 2] = f2tf32(rb1.z); Bs[nb][br + 8][bc + 3] = f2tf32(rb1.w);
            __syncthreads();
            buf = nb;
        }
    }

#pragma unroll
    for (int mt = 0; mt < 4; mt++) {
        const int row = crow0 + wm * 64 + mt * 16 + g;
#pragma unroll
        for (int nt = 0; nt < 4; nt++) {
            const int col = ccol0 + wn * 32 + nt * 8 + 2 * t;
            const float2 bv = *(const float2*)&bias[col];
            float2 o0, o1;
            o0.x = acc[mt][nt][0] + bv.x;
            o0.y = acc[mt][nt][1] + bv.y;
            o1.x = acc[mt][nt][2] + bv.x;
            o1.y = acc[mt][nt][3] + bv.y;
            *(float2*)&C[(size_t)row * N + col]       = o0;
            *(float2*)&C[(size_t)(row + 8) * N + col] = o1;
        }
    }
}

// ---------------------------------------------------------------------------
// Local trittention, tensor-core scores. One block per (bh, window n).
// 512 threads = 16 warps; warp q: S(32x32) = (a_l * c_q) @ b_l^T via
// mma.m16n8k8.tf32 (2 m-tiles x 4 n-tiles x 8 k-steps).
// ---------------------------------------------------------------------------
#define SPAD 68

__device__ __forceinline__ int bb_of(int n, int r) {
    return (r < WIN) ? ((n == 0) ? 0 : (n - 1) * WIN + r) : n * WIN + r - WIN;
}

__global__ __launch_bounds__(512)
void attn_kernel()
{
    __shared__ float    sa[32][SPAD];
    __shared__ unsigned sbt[32][SPAD];   // b_l pre-converted to tf32
    __shared__ float    sd[32][SPAD];
    __shared__ float    se[32][SPAD];
    __shared__ float    sc[16][SPAD];
    __shared__ float    spm[16][32];     // row marginals per warp
    __shared__ float    spl[16][32];     // col marginals per warp

    const int blk = blockIdx.x;
    const int n   = blk & (NWIN - 1);
    const int bh  = blk >> 7;
    const int b   = bh / NH;
    const int h   = bh % NH;
    const int tid = threadIdx.x;

    // ---- stage ----
    {
        int m  = tid >> 4;
        int c4 = (tid & 15) << 2;
        int t  = n * WIN + m - WIN;
        float4 z4 = make_float4(0.f, 0.f, 0.f, 0.f);
        float4 va = z4, vb = z4, vd = z4, ve = z4;
        if (t >= 0) {
            const float* base = g_abcde + ((size_t)(b * TT + t)) * (5 * DMODEL)
                              + h * DH + c4;
            va = *(const float4*)(base + 0 * DMODEL);
            vb = *(const float4*)(base + 1 * DMODEL);
            vd = *(const float4*)(base + 3 * DMODEL);
            ve = *(const float4*)(base + 4 * DMODEL);
        }
        *(float4*)&sa[m][c4] = va;
        sbt[m][c4 + 0] = f2tf32(vb.x);
        sbt[m][c4 + 1] = f2tf32(vb.y);
        sbt[m][c4 + 2] = f2tf32(vb.z);
        sbt[m][c4 + 3] = f2tf32(vb.w);
        *(float4*)&sd[m][c4] = vd;
        *(float4*)&se[m][c4] = ve;
        if (tid < 256) {
            int w  = tid >> 4;
            int cc = (tid & 15) << 2;
            int tq = n * WIN + w;
            const float* base = g_abcde + ((size_t)(b * TT + tq)) * (5 * DMODEL)
                              + 2 * DMODEL + h * DH + cc;
            *(float4*)&sc[w][cc] = *(const float4*)base;
        }
    }
    __syncthreads();

    const int q    = tid >> 5;
    const int lane = tid & 31;
    const int g    = lane >> 2;
    const int t    = lane & 3;
    const int qg   = n * WIN + q;

    float acc[2][4][4];
#pragma unroll
    for (int mt = 0; mt < 2; mt++)
#pragma unroll
        for (int nt = 0; nt < 4; nt++)
#pragma unroll
            for (int i = 0; i < 4; i++) acc[mt][nt][i] = 0.0f;

    // tensor-core scores
#pragma unroll
    for (int ks = 0; ks < 8; ks++) {
        const int k0 = ks * 8;
        const float c0 = sc[q][k0 + t];
        const float c1 = sc[q][k0 + t + 4];
        unsigned af[2][4];
#pragma unroll
        for (int mt = 0; mt < 2; mt++) {
            const int m0 = mt * 16;
            af[mt][0] = f2tf32(sa[m0 + g][k0 + t]     * c0);
            af[mt][1] = f2tf32(sa[m0 + g + 8][k0 + t] * c0);
            af[mt][2] = f2tf32(sa[m0 + g][k0 + t + 4]     * c1);
            af[mt][3] = f2tf32(sa[m0 + g + 8][k0 + t + 4] * c1);
        }
#pragma unroll
        for (int nt = 0; nt < 4; nt++) {
            unsigned bf[2];
            bf[0] = sbt[nt * 8 + g][k0 + t];
            bf[1] = sbt[nt * 8 + g][k0 + t + 4];
#pragma unroll
            for (int mt = 0; mt < 2; mt++)
                mma_tf32(acc[mt][nt], af[mt], bf);
        }
    }

    // mask + scale (C frag: rows g / g+8 (+16*mt), cols 8nt+2t / +1)
    int bbmA[2], bbmB[2], bbl[4][2];
#pragma unroll
    for (int mt = 0; mt < 2; mt++) {
        bbmA[mt] = bb_of(n, mt * 16 + g);
        bbmB[mt] = bb_of(n, mt * 16 + g + 8);
    }
#pragma unroll
    for (int nt = 0; nt < 4; nt++) {
        bbl[nt][0] = bb_of(n, nt * 8 + 2 * t);
        bbl[nt][1] = bb_of(n, nt * 8 + 2 * t + 1);
    }
#pragma unroll
    for (int mt = 0; mt < 2; mt++)
#pragma unroll
        for (int nt = 0; nt < 4; nt++)
#pragma unroll
            for (int i = 0; i < 4; i++) {
                const int bm = (i < 2) ? bbmA[mt] : bbmB[mt];
                const int bl = bbl[nt][i & 1];
                float s = acc[mt][nt][i];
                if ((qg < bl) || (bl <= bm) || (s == 0.0f)) s = IGNORE_V;
                acc[mt][nt][i] = s * (1.0f / 64.0f);
            }

    // softmax over all 1024 entries (32 per lane + warp reduce)
    float mx = acc[0][0][0];
#pragma unroll
    for (int mt = 0; mt < 2; mt++)
#pragma unroll
        for (int nt = 0; nt < 4; nt++)
#pragma unroll
            for (int i = 0; i < 4; i++) mx = fmaxf(mx, acc[mt][nt][i]);
#pragma unroll
    for (int off = 16; off; off >>= 1)
        mx = fmaxf(mx, __shfl_xor_sync(0xffffffffu, mx, off));

    float sum = 0.0f;
#pragma unroll
    for (int mt = 0; mt < 2; mt++)
#pragma unroll
        for (int nt = 0; nt < 4; nt++)
#pragma unroll
            for (int i = 0; i < 4; i++) {
                float e = __expf(acc[mt][nt][i] - mx);
                acc[mt][nt][i] = e;
                sum += e;
            }
#pragma unroll
    for (int off = 16; off; off >>= 1)
        sum += __shfl_xor_sync(0xffffffffu, sum, off);
    const float inv = 1.0f / sum;

    // row marginals (reduce over t: lanes xor 1,2), cols via xor 4,8,16
    float rA[2], rB[2];
#pragma unroll
    for (int mt = 0; mt < 2; mt++) {
        float a0 = 0.f, b0 = 0.f;
#pragma unroll
        for (int nt = 0; nt < 4; nt++) {
            a0 += acc[mt][nt][0] + acc[mt][nt][1];
            b0 += acc[mt][nt][2] + acc[mt][nt][3];
        }
#pragma unroll
        for (int off = 1; off <= 2; off <<= 1) {
            a0 += __shfl_xor_sync(0xffffffffu, a0, off);
            b0 += __shfl_xor_sync(0xffffffffu, b0, off);
        }
        rA[mt] = a0; rB[mt] = b0;
    }
    float cs[4][2];
#pragma unroll
    for (int nt = 0; nt < 4; nt++)
#pragma unroll
        for (int j = 0; j < 2; j++) {
            float v = acc[0][nt][j] + acc[0][nt][j + 2]
                    + acc[1][nt][j] + acc[1][nt][j + 2];
#pragma unroll
            for (int off = 4; off <= 16; off <<= 1)
                v += __shfl_xor_sync(0xffffffffu, v, off);
            cs[nt][j] = v;
        }

    if (t == 0) {
        spm[q][g]      = rA[0] * inv;
        spm[q][g + 8]  = rB[0] * inv;
        spm[q][g + 16] = rA[1] * inv;
        spm[q][g + 24] = rB[1] * inv;
    }
    if (g == 0) {
#pragma unroll
        for (int nt = 0; nt < 4; nt++) {
            spl[q][nt * 8 + 2 * t]     = cs[nt][0] * inv;
            spl[q][nt * 8 + 2 * t + 1] = cs[nt][1] * inv;
        }
    }
    __syncwarp();

    // z[d] = sum_m pm[m]*d_l[m,d] + sum_l pl[l]*e_l[l,d]
    float acc0 = 0.0f, acc1 = 0.0f;
#pragma unroll 1
    for (int m = 0; m < 32; m++) {
        const float pmv = spm[q][m];
        const float plv = spl[q][m];
        acc0 += pmv * sd[m][lane]      + plv * se[m][lane];
        acc1 += pmv * sd[m][lane + 32] + plv * se[m][lane + 32];
    }

    float* zrow = g_z + ((size_t)(b * TT + qg)) * (NH * DH) + h * DH;
    zrow[lane]      = acc0;
    zrow[lane + 32] = acc1;
}

// ---------------------------------------------------------------------------
extern "C" void kernel_launch(void* const* d_in, const int* in_sizes, int n_in,
                              void* d_out, int out_size)
{
    const float* x  = (const float*)d_in[0];
    const float* W1 = (const float*)d_in[1];
    const float* b1 = (const float*)d_in[2];
    const float* WO = (const float*)d_in[3];
    const float* bO = (const float*)d_in[4];
    float* out = (float*)d_out;

    float* abcde = nullptr;
    float* zbuf  = nullptr;
    cudaGetSymbolAddress((void**)&abcde, g_abcde);
    cudaGetSymbolAddress((void**)&zbuf,  g_z);

    const int M = BB * TT;

    gemm_tf32<<<dim3((5 * NH * DH) / 128, M / 128), 256>>>(
        x, W1, b1, abcde, M, 5 * NH * DH, DMODEL);

    attn_kernel<<<BB * NH * NWIN, 512>>>();

    gemm_tf32<<<dim3(DMODEL / 128, M / 128), 256>>>(
        zbuf, WO, bO, out, M, DMODEL, NH * DH);
}

// round 5
// speedup vs baseline: 3.6862x; 1.2217x over previous
#include <cuda_runtime.h>
#include <cstdint>

#define DMODEL 768
#define NH     12
#define DH     64
#define WIN    16
#define NWIN   128
#define BB     2
#define TT     2048
#define IGNORE_V (-1.0e6f)

// Scratch (device globals: allocation-free)
__device__ float g_abcde[(size_t)BB * TT * 5 * NH * DH]; // 62.9 MB
__device__ float g_z[(size_t)BB * TT * NH * DH];         // 12.6 MB
__device__ float g_xp[(size_t)BB * TT * DMODEL];         // x packed (A-frag)
__device__ float g_zp[(size_t)BB * TT * DMODEL];         // z packed (A-frag)
__device__ float g_w1p[(size_t)DMODEL * 5 * NH * DH];    // W1 packed (B-frag)
__device__ float g_wop[(size_t)DMODEL * DMODEL];         // WO packed (B-frag)

// ---------------------------------------------------------------------------
__device__ __forceinline__ unsigned f2tf32(float x) {
    unsigned r;
    asm("cvt.rna.tf32.f32 %0, %1;" : "=r"(r) : "f"(x));
    return r;
}
__device__ __forceinline__ unsigned smem_u32(const void* p) {
    unsigned a;
    asm("{ .reg .u64 t; cvta.to.shared.u64 t, %1; cvt.u32.u64 %0, t; }" : "=r"(a) : "l"(p));
    return a;
}
__device__ __forceinline__ void cp16(void* s, const void* g) {
    asm volatile("cp.async.cg.shared.global [%0], [%1], 16;"
                 :: "r"(smem_u32(s)), "l"(g) : "memory");
}
__device__ __forceinline__ void mma_tf32(float c[4], const unsigned a[4], const unsigned b[2]) {
    asm volatile(
        "mma.sync.aligned.m16n8k8.row.col.f32.tf32.tf32.f32 "
        "{%0,%1,%2,%3}, {%4,%5,%6,%7}, {%8,%9}, {%0,%1,%2,%3};"
        : "+f"(c[0]), "+f"(c[1]), "+f"(c[2]), "+f"(c[3])
        : "r"(a[0]), "r"(a[1]), "r"(a[2]), "r"(a[3]), "r"(b[0]), "r"(b[1]));
}

// ---------------------------------------------------------------------------
// pack_a: A (R x K) row-major fp32 -> A-fragment layout, tf32-rounded.
// Output quad (16B) per (stripe, kslice, i, lane): regs
//   [ (g,t), (g+8,t), (g,t+4), (g+8,t+4) ]  with lane = g*4+t.
// grid = (nks = K/8, nstripes = R/128), block 256 (i = tid>>5, lane = tid&31).
// ---------------------------------------------------------------------------
__global__ __launch_bounds__(256)
void pack_a(const float* __restrict__ in, float* __restrict__ out, int K)
{
    const int ks = blockIdx.x, stripe = blockIdx.y, nks = gridDim.x;
    const int tid = threadIdx.x;
    const int i = tid >> 5, lane = tid & 31;
    const int g = lane >> 2, t = lane & 3;
    const int row = stripe * 128 + i * 16 + g;
    const int col = ks * 8 + t;
    const float* p = in + (size_t)row * K + col;
    uint4 o;
    o.x = f2tf32(p[0]);
    o.y = f2tf32(p[(size_t)8 * K]);
    o.z = f2tf32(p[4]);
    o.w = f2tf32(p[(size_t)8 * K + 4]);
    ((uint4*)out)[((size_t)(stripe * nks + ks) * 8 + i) * 32 + lane] = o;
}

// ---------------------------------------------------------------------------
// pack_b: W (K x N) row-major fp32 -> B-fragment layout, tf32-rounded.
// Output pair (8B) per (cblk, kslice, j, lane): regs [ (k+t,n), (k+t+4,n) ],
// lane = g*4+t, n = cblk*128 + j*8 + g.
// grid = (nks = K/8, ncb = N/128), block 256 (each thread handles j and j+8).
// ---------------------------------------------------------------------------
__global__ __launch_bounds__(256)
void pack_b(const float* __restrict__ in, float* __restrict__ out, int N)
{
    const int ks = blockIdx.x, cb = blockIdx.y, nks = gridDim.x;
    const int tid = threadIdx.x;
    const int j0 = tid >> 5, lane = tid & 31;
    const int g = lane >> 2, t = lane & 3;
    const int k = ks * 8 + t;
#pragma unroll
    for (int jj = j0; jj < 16; jj += 8) {
        const int n = cb * 128 + jj * 8 + g;
        uint2 o;
        o.x = f2tf32(in[(size_t)k * N + n]);
        o.y = f2tf32(in[(size_t)(k + 4) * N + n]);
        ((uint2*)out)[((size_t)(cb * nks + ks) * 16 + jj) * 32 + lane] = o;
    }
}

// ---------------------------------------------------------------------------
// gemm_frag: C(MxN) = Ap @ Bp + bias using pre-packed fragment operands.
// Block 128x128, BK=32 (4 kslices/iter), 8 warps (2x4), warp tile 64x32.
// 3-stage cp.async pipeline (32KB/stage, 96KB dynamic smem).
// ---------------------------------------------------------------------------
#define GSMEM (3 * 32768)

__global__ __launch_bounds__(256)
void gemm_frag(const float* __restrict__ Ap, const float* __restrict__ Bp,
               const float* __restrict__ bias, float* __restrict__ C,
               int M, int N, int K)
{
    extern __shared__ float4 dsm[];   // [3][2048] float4: A(1024) then B(1024)

    const int nks  = K >> 3;
    const int nIt  = K >> 5;          // BK = 32
    const int tid  = threadIdx.x;
    const int lane = tid & 31;
    const int wid  = tid >> 5;
    const int wm   = wid & 1;
    const int wn   = wid >> 1;
    const int g    = lane >> 2;
    const int t    = lane & 3;
    const int bN   = blockIdx.x, bM = blockIdx.y;

    // per-(stripe|cblk, kslice) block = 256 float4; per iter (4 kslices) = 1024 float4
    const float4* Ag = (const float4*)Ap + (size_t)bM * nks * 256;
    const float4* Bg = (const float4*)Bp + (size_t)bN * nks * 256;

    float acc[4][4][4];
#pragma unroll
    for (int mt = 0; mt < 4; mt++)
#pragma unroll
        for (int nt = 0; nt < 4; nt++)
#pragma unroll
            for (int i = 0; i < 4; i++) acc[mt][nt][i] = 0.0f;

    // prologue: stages 0,1
#pragma unroll
    for (int s = 0; s < 2; s++) {
        const float4* ga = Ag + (size_t)s * 1024 + tid;
        const float4* gb = Bg + (size_t)s * 1024 + tid;
        float4* sa = dsm + s * 2048 + tid;
        float4* sb = dsm + s * 2048 + 1024 + tid;
#pragma unroll
        for (int r = 0; r < 4; r++) {
            cp16(sa + 256 * r, ga + 256 * r);
            cp16(sb + 256 * r, gb + 256 * r);
        }
        asm volatile("cp.async.commit_group;" ::: "memory");
    }

    int st = 0;
    for (int it = 0; it < nIt; it++) {
        if (it + 1 < nIt) asm volatile("cp.async.wait_group 1;" ::: "memory");
        else              asm volatile("cp.async.wait_group 0;" ::: "memory");
        __syncthreads();

        if (it + 2 < nIt) {
            const int ns = (it + 2) % 3;
            const float4* ga = Ag + (size_t)(it + 2) * 1024 + tid;
            const float4* gb = Bg + (size_t)(it + 2) * 1024 + tid;
            float4* sa = dsm + ns * 2048 + tid;
            float4* sb = dsm + ns * 2048 + 1024 + tid;
#pragma unroll
            for (int r = 0; r < 4; r++) {
                cp16(sa + 256 * r, ga + 256 * r);
                cp16(sb + 256 * r, gb + 256 * r);
            }
            asm volatile("cp.async.commit_group;" ::: "memory");
        }

        const uint4* sA = (const uint4*)(dsm + st * 2048);
        const uint2* sB = (const uint2*)(dsm + st * 2048 + 1024);
#pragma unroll
        for (int ks = 0; ks < 4; ks++) {
            uint4 af[4];
            uint2 bf[4];
#pragma unroll
            for (int mt = 0; mt < 4; mt++)
                af[mt] = sA[(ks * 8 + wm * 4 + mt) * 32 + lane];
#pragma unroll
            for (int nt = 0; nt < 4; nt++)
                bf[nt] = sB[(ks * 16 + wn * 4 + nt) * 32 + lane];
#pragma unroll
            for (int mt = 0; mt < 4; mt++)
#pragma unroll
                for (int nt = 0; nt < 4; nt++)
                    mma_tf32(acc[mt][nt], (const unsigned*)&af[mt],
                             (const unsigned*)&bf[nt]);
        }
        st = (st + 1) % 3;
    }

    // epilogue: c0,c1 at (row, 2t..2t+1); c2,c3 at (row+8, ...)
    const int crow0 = bM * 128, ccol0 = bN * 128;
#pragma unroll
    for (int mt = 0; mt < 4; mt++) {
        const int row = crow0 + wm * 64 + mt * 16 + g;
#pragma unroll
        for (int nt = 0; nt < 4; nt++) {
            const int col = ccol0 + wn * 32 + nt * 8 + 2 * t;
            const float2 bv = *(const float2*)&bias[col];
            float2 o0, o1;
            o0.x = acc[mt][nt][0] + bv.x;
            o0.y = acc[mt][nt][1] + bv.y;
            o1.x = acc[mt][nt][2] + bv.x;
            o1.y = acc[mt][nt][3] + bv.y;
            *(float2*)&C[(size_t)row * N + col]       = o0;
            *(float2*)&C[(size_t)(row + 8) * N + col] = o1;
        }
    }
}

// ---------------------------------------------------------------------------
// Local trittention (round-3 version, tensor-core scores + marginals).
// ---------------------------------------------------------------------------
#define SPAD 68

__device__ __forceinline__ int bb_of(int n, int r) {
    return (r < WIN) ? ((n == 0) ? 0 : (n - 1) * WIN + r) : n * WIN + r - WIN;
}

__global__ __launch_bounds__(512)
void attn_kernel()
{
    __shared__ float    sa[32][SPAD];
    __shared__ unsigned sbt[32][SPAD];
    __shared__ float    sd[32][SPAD];
    __shared__ float    se[32][SPAD];
    __shared__ float    sc[16][SPAD];
    __shared__ float    spm[16][32];
    __shared__ float    spl[16][32];

    const int blk = blockIdx.x;
    const int n   = blk & (NWIN - 1);
    const int bh  = blk >> 7;
    const int b   = bh / NH;
    const int h   = bh % NH;
    const int tid = threadIdx.x;

    {
        int m  = tid >> 4;
        int c4 = (tid & 15) << 2;
        int t  = n * WIN + m - WIN;
        float4 z4 = make_float4(0.f, 0.f, 0.f, 0.f);
        float4 va = z4, vb = z4, vd = z4, ve = z4;
        if (t >= 0) {
            const float* base = g_abcde + ((size_t)(b * TT + t)) * (5 * DMODEL)
                              + h * DH + c4;
            va = *(const float4*)(base + 0 * DMODEL);
            vb = *(const float4*)(base + 1 * DMODEL);
            vd = *(const float4*)(base + 3 * DMODEL);
            ve = *(const float4*)(base + 4 * DMODEL);
        }
        *(float4*)&sa[m][c4] = va;
        sbt[m][c4 + 0] = f2tf32(vb.x);
        sbt[m][c4 + 1] = f2tf32(vb.y);
        sbt[m][c4 + 2] = f2tf32(vb.z);
        sbt[m][c4 + 3] = f2tf32(vb.w);
        *(float4*)&sd[m][c4] = vd;
        *(float4*)&se[m][c4] = ve;
        if (tid < 256) {
            int w  = tid >> 4;
            int cc = (tid & 15) << 2;
            int tq = n * WIN + w;
            const float* base = g_abcde + ((size_t)(b * TT + tq)) * (5 * DMODEL)
                              + 2 * DMODEL + h * DH + cc;
            *(float4*)&sc[w][cc] = *(const float4*)base;
        }
    }
    __syncthreads();

    const int q    = tid >> 5;
    const int lane = tid & 31;
    const int g    = lane >> 2;
    const int t    = lane & 3;
    const int qg   = n * WIN + q;

    float acc[2][4][4];
#pragma unroll
    for (int mt = 0; mt < 2; mt++)
#pragma unroll
        for (int nt = 0; nt < 4; nt++)
#pragma unroll
            for (int i = 0; i < 4; i++) acc[mt][nt][i] = 0.0f;

#pragma unroll
    for (int ks = 0; ks < 8; ks++) {
        const int k0 = ks * 8;
        const float c0 = sc[q][k0 + t];
        const float c1 = sc[q][k0 + t + 4];
        unsigned af[2][4];
#pragma unroll
        for (int mt = 0; mt < 2; mt++) {
            const int m0 = mt * 16;
            af[mt][0] = f2tf32(sa[m0 + g][k0 + t]     * c0);
            af[mt][1] = f2tf32(sa[m0 + g + 8][k0 + t] * c0);
            af[mt][2] = f2tf32(sa[m0 + g][k0 + t + 4]     * c1);
            af[mt][3] = f2tf32(sa[m0 + g + 8][k0 + t + 4] * c1);
        }
#pragma unroll
        for (int nt = 0; nt < 4; nt++) {
            unsigned bf[2];
            bf[0] = sbt[nt * 8 + g][k0 + t];
            bf[1] = sbt[nt * 8 + g][k0 + t + 4];
#pragma unroll
            for (int mt = 0; mt < 2; mt++)
                mma_tf32(acc[mt][nt], af[mt], bf);
        }
    }

    int bbmA[2], bbmB[2], bbl[4][2];
#pragma unroll
    for (int mt = 0; mt < 2; mt++) {
        bbmA[mt] = bb_of(n, mt * 16 + g);
        bbmB[mt] = bb_of(n, mt * 16 + g + 8);
    }
#pragma unroll
    for (int nt = 0; nt < 4; nt++) {
        bbl[nt][0] = bb_of(n, nt * 8 + 2 * t);
        bbl[nt][1] = bb_of(n, nt * 8 + 2 * t + 1);
    }
#pragma unroll
    for (int mt = 0; mt < 2; mt++)
#pragma unroll
        for (int nt = 0; nt < 4; nt++)
#pragma unroll
            for (int i = 0; i < 4; i++) {
                const int bm = (i < 2) ? bbmA[mt] : bbmB[mt];
                const int bl = bbl[nt][i & 1];
                float s = acc[mt][nt][i];
                if ((qg < bl) || (bl <= bm) || (s == 0.0f)) s = IGNORE_V;
                acc[mt][nt][i] = s * (1.0f / 64.0f);
            }

    float mx = acc[0][0][0];
#pragma unroll
    for (int mt = 0; mt < 2; mt++)
#pragma unroll
        for (int nt = 0; nt < 4; nt++)
#pragma unroll
            for (int i = 0; i < 4; i++) mx = fmaxf(mx, acc[mt][nt][i]);
#pragma unroll
    for (int off = 16; off; off >>= 1)
        mx = fmaxf(mx, __shfl_xor_sync(0xffffffffu, mx, off));

    float sum = 0.0f;
#pragma unroll
    for (int mt = 0; mt < 2; mt++)
#pragma unroll
        for (int nt = 0; nt < 4; nt++)
#pragma unroll
            for (int i = 0; i < 4; i++) {
                float e = __expf(acc[mt][nt][i] - mx);
                acc[mt][nt][i] = e;
                sum += e;
            }
#pragma unroll
    for (int off = 16; off; off >>= 1)
        sum += __shfl_xor_sync(0xffffffffu, sum, off);
    const float inv = 1.0f / sum;

    float rA[2], rB[2];
#pragma unroll
    for (int mt = 0; mt < 2; mt++) {
        float a0 = 0.f, b0 = 0.f;
#pragma unroll
        for (int nt = 0; nt < 4; nt++) {
            a0 += acc[mt][nt][0] + acc[mt][nt][1];
            b0 += acc[mt][nt][2] + acc[mt][nt][3];
        }
#pragma unroll
        for (int off = 1; off <= 2; off <<= 1) {
            a0 += __shfl_xor_sync(0xffffffffu, a0, off);
            b0 += __shfl_xor_sync(0xffffffffu, b0, off);
        }
        rA[mt] = a0; rB[mt] = b0;
    }
    float cs[4][2];
#pragma unroll
    for (int nt = 0; nt < 4; nt++)
#pragma unroll
        for (int j = 0; j < 2; j++) {
            float v = acc[0][nt][j] + acc[0][nt][j + 2]
                    + acc[1][nt][j] + acc[1][nt][j + 2];
#pragma unroll
            for (int off = 4; off <= 16; off <<= 1)
                v += __shfl_xor_sync(0xffffffffu, v, off);
            cs[nt][j] = v;
        }

    if (t == 0) {
        spm[q][g]      = rA[0] * inv;
        spm[q][g + 8]  = rB[0] * inv;
        spm[q][g + 16] = rA[1] * inv;
        spm[q][g + 24] = rB[1] * inv;
    }
    if (g == 0) {
#pragma unroll
        for (int nt = 0; nt < 4; nt++) {
            spl[q][nt * 8 + 2 * t]     = cs[nt][0] * inv;
            spl[q][nt * 8 + 2 * t + 1] = cs[nt][1] * inv;
        }
    }
    __syncwarp();

    float acc0 = 0.0f, acc1 = 0.0f;
#pragma unroll 1
    for (int m = 0; m < 32; m++) {
        const float pmv = spm[q][m];
        const float plv = spl[q][m];
        acc0 += pmv * sd[m][lane]      + plv * se[m][lane];
        acc1 += pmv * sd[m][lane + 32] + plv * se[m][lane + 32];
    }

    float* zrow = g_z + ((size_t)(b * TT + qg)) * (NH * DH) + h * DH;
    zrow[lane]      = acc0;
    zrow[lane + 32] = acc1;
}

// ---------------------------------------------------------------------------
extern "C" void kernel_launch(void* const* d_in, const int* in_sizes, int n_in,
                              void* d_out, int out_size)
{
    const float* x  = (const float*)d_in[0];  // (2,2048,768)
    const float* W1 = (const float*)d_in[1];  // (768, 3840)
    const float* b1 = (const float*)d_in[2];  // (3840)
    const float* WO = (const float*)d_in[3];  // (768, 768)
    const float* bO = (const float*)d_in[4];  // (768)
    float* out = (float*)d_out;               // (2,2048,768)

    float *abcde, *zbuf, *xp, *zp, *w1p, *wop;
    cudaGetSymbolAddress((void**)&abcde, g_abcde);
    cudaGetSymbolAddress((void**)&zbuf,  g_z);
    cudaGetSymbolAddress((void**)&xp,    g_xp);
    cudaGetSymbolAddress((void**)&zp,    g_zp);
    cudaGetSymbolAddress((void**)&w1p,   g_w1p);
    cudaGetSymbolAddress((void**)&wop,   g_wop);

    static bool attr_done = false;
    if (!attr_done) {
        cudaFuncSetAttribute(gemm_frag,
                             cudaFuncAttributeMaxDynamicSharedMemorySize, GSMEM);
        attr_done = true;
    }

    const int M  = BB * TT;          // 4096
    const int N1 = 5 * NH * DH;      // 3840
    const int N2 = DMODEL;           // 768
    const int K  = DMODEL;           // 768 (both GEMMs)
    const int nks = K / 8;           // 96

    // pack operands (tf32-rounded, fragment order)
    pack_a<<<dim3(nks, M / 128), 256>>>(x, xp, K);
    pack_b<<<dim3(nks, N1 / 128), 256>>>(W1, w1p, N1);
    pack_b<<<dim3(nks, N2 / 128), 256>>>(WO, wop, N2);

    // 1) abcde = x @ W1 + b1
    gemm_frag<<<dim3(N1 / 128, M / 128), 256, GSMEM>>>(xp, w1p, b1, abcde, M, N1, K);

    // 2) local trittention -> z
    attn_kernel<<<BB * NH * NWIN, 512>>>();

    // 3) pack z, then out = z @ WO + bO
    pack_a<<<dim3(nks, M / 128), 256>>>(zbuf, zp, K);
    gemm_frag<<<dim3(N2 / 128, M / 128), 256, GSMEM>>>(zp, wop, bO, out, M, N2, K);
}

// round 6
// speedup vs baseline: 3.8455x; 1.0432x over previous
#include <cuda_runtime.h>
#include <cstdint>

#define DMODEL 768
#define NH     12
#define DH     64
#define WIN    16
#define NWIN   128
#define BB     2
#define TT     2048
#define IGNORE_V (-1.0e6f)

// Scratch (device globals: allocation-free)
__device__ float g_abcde[(size_t)BB * TT * 5 * NH * DH]; // 62.9 MB
__device__ float g_xp[(size_t)BB * TT * DMODEL];         // x packed (A-frag)
__device__ float g_zp[(size_t)BB * TT * DMODEL];         // z packed (A-frag), written by attn
__device__ float g_w1p[(size_t)DMODEL * 5 * NH * DH];    // W1 packed (B-frag)
__device__ float g_wop[(size_t)DMODEL * DMODEL];         // WO packed (B-frag)

// ---------------------------------------------------------------------------
__device__ __forceinline__ unsigned f2tf32(float x) {
    unsigned r;
    asm("cvt.rna.tf32.f32 %0, %1;" : "=r"(r) : "f"(x));
    return r;
}
__device__ __forceinline__ unsigned smem_u32(const void* p) {
    unsigned a;
    asm("{ .reg .u64 t; cvta.to.shared.u64 t, %1; cvt.u32.u64 %0, t; }" : "=r"(a) : "l"(p));
    return a;
}
__device__ __forceinline__ void cp16(void* s, const void* g) {
    asm volatile("cp.async.cg.shared.global [%0], [%1], 16;"
                 :: "r"(smem_u32(s)), "l"(g) : "memory");
}
__device__ __forceinline__ void mma_tf32(float c[4], const unsigned a[4], const unsigned b[2]) {
    asm volatile(
        "mma.sync.aligned.m16n8k8.row.col.f32.tf32.tf32.f32 "
        "{%0,%1,%2,%3}, {%4,%5,%6,%7}, {%8,%9}, {%0,%1,%2,%3};"
        : "+f"(c[0]), "+f"(c[1]), "+f"(c[2]), "+f"(c[3])
        : "r"(a[0]), "r"(a[1]), "r"(a[2]), "r"(a[3]), "r"(b[0]), "r"(b[1]));
}

// ---------------------------------------------------------------------------
// pack_a: A (R x K) row-major fp32 -> A-fragment layout, tf32-rounded.
// quad (16B) at ((stripe*nks+ks)*8+i)*32+lane  holds
//   [ (i16+g, 8ks+t), (i16+g+8, 8ks+t), (i16+g, 8ks+t+4), (i16+g+8, 8ks+t+4) ]
// ---------------------------------------------------------------------------
__global__ __launch_bounds__(256)
void pack_a(const float* __restrict__ in, float* __restrict__ out, int K)
{
    const int ks = blockIdx.x, stripe = blockIdx.y, nks = gridDim.x;
    const int tid = threadIdx.x;
    const int i = tid >> 5, lane = tid & 31;
    const int g = lane >> 2, t = lane & 3;
    const int row = stripe * 128 + i * 16 + g;
    const int col = ks * 8 + t;
    const float* p = in + (size_t)row * K + col;
    uint4 o;
    o.x = f2tf32(p[0]);
    o.y = f2tf32(p[(size_t)8 * K]);
    o.z = f2tf32(p[4]);
    o.w = f2tf32(p[(size_t)8 * K + 4]);
    ((uint4*)out)[((size_t)(stripe * nks + ks) * 8 + i) * 32 + lane] = o;
}

// ---------------------------------------------------------------------------
// pack_b: W (K x N) row-major fp32 -> B-fragment layout, tf32-rounded.
// ---------------------------------------------------------------------------
__global__ __launch_bounds__(256)
void pack_b(const float* __restrict__ in, float* __restrict__ out, int N)
{
    const int ks = blockIdx.x, cb = blockIdx.y, nks = gridDim.x;
    const int tid = threadIdx.x;
    const int j0 = tid >> 5, lane = tid & 31;
    const int g = lane >> 2, t = lane & 3;
    const int k = ks * 8 + t;
#pragma unroll
    for (int jj = j0; jj < 16; jj += 8) {
        const int n = cb * 128 + jj * 8 + g;
        uint2 o;
        o.x = f2tf32(in[(size_t)k * N + n]);
        o.y = f2tf32(in[(size_t)(k + 4) * N + n]);
        ((uint2*)out)[((size_t)(cb * nks + ks) * 16 + jj) * 32 + lane] = o;
    }
}

// ---------------------------------------------------------------------------
// gemm_frag: C(MxN) = Ap @ Bp + bias using pre-packed fragment operands.
// Block 128x128, BK=32, 8 warps (2x4), warp tile 64x32, 3-stage cp.async.
// ---------------------------------------------------------------------------
#define GSMEM (3 * 32768)

__global__ __launch_bounds__(256)
void gemm_frag(const float* __restrict__ Ap, const float* __restrict__ Bp,
               const float* __restrict__ bias, float* __restrict__ C,
               int M, int N, int K)
{
    extern __shared__ float4 dsm[];

    const int nks  = K >> 3;
    const int nIt  = K >> 5;
    const int tid  = threadIdx.x;
    const int lane = tid & 31;
    const int wid  = tid >> 5;
    const int wm   = wid & 1;
    const int wn   = wid >> 1;
    const int g    = lane >> 2;
    const int t    = lane & 3;
    const int bN   = blockIdx.x, bM = blockIdx.y;

    const float4* Ag = (const float4*)Ap + (size_t)bM * nks * 256;
    const float4* Bg = (const float4*)Bp + (size_t)bN * nks * 256;

    float acc[4][4][4];
#pragma unroll
    for (int mt = 0; mt < 4; mt++)
#pragma unroll
        for (int nt = 0; nt < 4; nt++)
#pragma unroll
            for (int i = 0; i < 4; i++) acc[mt][nt][i] = 0.0f;

#pragma unroll
    for (int s = 0; s < 2; s++) {
        const float4* ga = Ag + (size_t)s * 1024 + tid;
        const float4* gb = Bg + (size_t)s * 1024 + tid;
        float4* sa = dsm + s * 2048 + tid;
        float4* sb = dsm + s * 2048 + 1024 + tid;
#pragma unroll
        for (int r = 0; r < 4; r++) {
            cp16(sa + 256 * r, ga + 256 * r);
            cp16(sb + 256 * r, gb + 256 * r);
        }
        asm volatile("cp.async.commit_group;" ::: "memory");
    }

    int st = 0;
    for (int it = 0; it < nIt; it++) {
        if (it + 1 < nIt) asm volatile("cp.async.wait_group 1;" ::: "memory");
        else              asm volatile("cp.async.wait_group 0;" ::: "memory");
        __syncthreads();

        if (it + 2 < nIt) {
            const int ns = (it + 2) % 3;
            const float4* ga = Ag + (size_t)(it + 2) * 1024 + tid;
            const float4* gb = Bg + (size_t)(it + 2) * 1024 + tid;
            float4* sa = dsm + ns * 2048 + tid;
            float4* sb = dsm + ns * 2048 + 1024 + tid;
#pragma unroll
            for (int r = 0; r < 4; r++) {
                cp16(sa + 256 * r, ga + 256 * r);
                cp16(sb + 256 * r, gb + 256 * r);
            }
            asm volatile("cp.async.commit_group;" ::: "memory");
        }

        const uint4* sA = (const uint4*)(dsm + st * 2048);
        const uint2* sB = (const uint2*)(dsm + st * 2048 + 1024);
#pragma unroll
        for (int ks = 0; ks < 4; ks++) {
            uint4 af[4];
            uint2 bf[4];
#pragma unroll
            for (int mt = 0; mt < 4; mt++)
                af[mt] = sA[(ks * 8 + wm * 4 + mt) * 32 + lane];
#pragma unroll
            for (int nt = 0; nt < 4; nt++)
                bf[nt] = sB[(ks * 16 + wn * 4 + nt) * 32 + lane];
#pragma unroll
            for (int mt = 0; mt < 4; mt++)
#pragma unroll
                for (int nt = 0; nt < 4; nt++)
                    mma_tf32(acc[mt][nt], (const unsigned*)&af[mt],
                             (const unsigned*)&bf[nt]);
        }
        st = (st + 1) % 3;
    }

    const int crow0 = bM * 128, ccol0 = bN * 128;
#pragma unroll
    for (int mt = 0; mt < 4; mt++) {
        const int row = crow0 + wm * 64 + mt * 16 + g;
#pragma unroll
        for (int nt = 0; nt < 4; nt++) {
            const int col = ccol0 + wn * 32 + nt * 8 + 2 * t;
            const float2 bv = *(const float2*)&bias[col];
            float2 o0, o1;
            o0.x = acc[mt][nt][0] + bv.x;
            o0.y = acc[mt][nt][1] + bv.y;
            o1.x = acc[mt][nt][2] + bv.x;
            o1.y = acc[mt][nt][3] + bv.y;
            *(float2*)&C[(size_t)row * N + col]       = o0;
            *(float2*)&C[(size_t)(row + 8) * N + col] = o1;
        }
    }
}

// ---------------------------------------------------------------------------
// Local trittention. One block per (bh, window). 512 thr, min 2 blocks/SM.
// Warp q: S(32x32) = (a_l*c_q) @ b_l^T via mma; softmax; marginal epilogue
// writes z directly in packed A-fragment layout (tf32-rounded).
// ---------------------------------------------------------------------------
#define SPAD 68

__global__ __launch_bounds__(512, 2)
void attn_kernel()
{
    __shared__ float    sa[32][SPAD];
    __shared__ unsigned sbt[32][SPAD];
    __shared__ float    sd[32][SPAD];
    __shared__ float    se[32][SPAD];
    __shared__ float    sc[16][SPAD];
    __shared__ float    spm[16][32];
    __shared__ float    spl[16][32];
    __shared__ int      sbb[32];

    const int blk = blockIdx.x;
    const int n   = blk & (NWIN - 1);
    const int bh  = blk >> 7;
    const int b   = bh / NH;
    const int h   = bh % NH;
    const int tid = threadIdx.x;

    {
        int m  = tid >> 4;
        int c4 = (tid & 15) << 2;
        int t  = n * WIN + m - WIN;
        float4 z4 = make_float4(0.f, 0.f, 0.f, 0.f);
        float4 va = z4, vb = z4, vd = z4, ve = z4;
        if (t >= 0) {
            const float* base = g_abcde + ((size_t)(b * TT + t)) * (5 * DMODEL)
                              + h * DH + c4;
            va = *(const float4*)(base + 0 * DMODEL);
            vb = *(const float4*)(base + 1 * DMODEL);
            vd = *(const float4*)(base + 3 * DMODEL);
            ve = *(const float4*)(base + 4 * DMODEL);
        }
        *(float4*)&sa[m][c4] = va;
        sbt[m][c4 + 0] = f2tf32(vb.x);
        sbt[m][c4 + 1] = f2tf32(vb.y);
        sbt[m][c4 + 2] = f2tf32(vb.z);
        sbt[m][c4 + 3] = f2tf32(vb.w);
        *(float4*)&sd[m][c4] = vd;
        *(float4*)&se[m][c4] = ve;
        if (tid < 256) {
            int w  = tid >> 4;
            int cc = (tid & 15) << 2;
            int tq = n * WIN + w;
            const float* base = g_abcde + ((size_t)(b * TT + tq)) * (5 * DMODEL)
                              + 2 * DMODEL + h * DH + cc;
            *(float4*)&sc[w][cc] = *(const float4*)base;
        }
        if (tid < 32) {
            // look-around token index of row tid (pads use 0)
            sbb[tid] = (tid < WIN) ? ((n == 0) ? 0 : (n - 1) * WIN + tid)
                                   : n * WIN + tid - WIN;
        }
    }
    __syncthreads();

    const int q    = tid >> 5;
    const int lane = tid & 31;
    const int g    = lane >> 2;
    const int t    = lane & 3;
    const int qg   = n * WIN + q;

    float acc[2][4][4];
#pragma unroll
    for (int mt = 0; mt < 2; mt++)
#pragma unroll
        for (int nt = 0; nt < 4; nt++)
#pragma unroll
            for (int i = 0; i < 4; i++) acc[mt][nt][i] = 0.0f;

#pragma unroll
    for (int ks = 0; ks < 8; ks++) {
        const int k0 = ks * 8;
        const float c0 = sc[q][k0 + t];
        const float c1 = sc[q][k0 + t + 4];
        unsigned af[2][4];
#pragma unroll
        for (int mt = 0; mt < 2; mt++) {
            const int m0 = mt * 16;
            af[mt][0] = f2tf32(sa[m0 + g][k0 + t]     * c0);
            af[mt][1] = f2tf32(sa[m0 + g + 8][k0 + t] * c0);
            af[mt][2] = f2tf32(sa[m0 + g][k0 + t + 4]     * c1);
            af[mt][3] = f2tf32(sa[m0 + g + 8][k0 + t + 4] * c1);
        }
#pragma unroll
        for (int nt = 0; nt < 4; nt++) {
            unsigned bf[2];
            bf[0] = sbt[nt * 8 + g][k0 + t];
            bf[1] = sbt[nt * 8 + g][k0 + t + 4];
#pragma unroll
            for (int mt = 0; mt < 2; mt++)
                mma_tf32(acc[mt][nt], af[mt], bf);
        }
    }

    // mask + scale; bb values from smem table
#pragma unroll
    for (int mt = 0; mt < 2; mt++)
#pragma unroll
        for (int nt = 0; nt < 4; nt++)
#pragma unroll
            for (int i = 0; i < 4; i++) {
                const int bm = sbb[mt * 16 + g + ((i < 2) ? 0 : 8)];
                const int bl = sbb[nt * 8 + 2 * t + (i & 1)];
                float s = acc[mt][nt][i];
                if ((qg < bl) || (bl <= bm) || (s == 0.0f)) s = IGNORE_V;
                acc[mt][nt][i] = s * (1.0f / 64.0f);
            }

    float mx = acc[0][0][0];
#pragma unroll
    for (int mt = 0; mt < 2; mt++)
#pragma unroll
        for (int nt = 0; nt < 4; nt++)
#pragma unroll
            for (int i = 0; i < 4; i++) mx = fmaxf(mx, acc[mt][nt][i]);
#pragma unroll
    for (int off = 16; off; off >>= 1)
        mx = fmaxf(mx, __shfl_xor_sync(0xffffffffu, mx, off));

    float sum = 0.0f;
#pragma unroll
    for (int mt = 0; mt < 2; mt++)
#pragma unroll
        for (int nt = 0; nt < 4; nt++)
#pragma unroll
            for (int i = 0; i < 4; i++) {
                float e = __expf(acc[mt][nt][i] - mx);
                acc[mt][nt][i] = e;
                sum += e;
            }
#pragma unroll
    for (int off = 16; off; off >>= 1)
        sum += __shfl_xor_sync(0xffffffffu, sum, off);
    const float inv = 1.0f / sum;

    float rA[2], rB[2];
#pragma unroll
    for (int mt = 0; mt < 2; mt++) {
        float a0 = 0.f, b0 = 0.f;
#pragma unroll
        for (int nt = 0; nt < 4; nt++) {
            a0 += acc[mt][nt][0] + acc[mt][nt][1];
            b0 += acc[mt][nt][2] + acc[mt][nt][3];
        }
#pragma unroll
        for (int off = 1; off <= 2; off <<= 1) {
            a0 += __shfl_xor_sync(0xffffffffu, a0, off);
            b0 += __shfl_xor_sync(0xffffffffu, b0, off);
        }
        rA[mt] = a0; rB[mt] = b0;
    }
    float cs[4][2];
#pragma unroll
    for (int nt = 0; nt < 4; nt++)
#pragma unroll
        for (int j = 0; j < 2; j++) {
            float v = acc[0][nt][j] + acc[0][nt][j + 2]
                    + acc[1][nt][j] + acc[1][nt][j + 2];
#pragma unroll
            for (int off = 4; off <= 16; off <<= 1)
                v += __shfl_xor_sync(0xffffffffu, v, off);
            cs[nt][j] = v;
        }

    if (t == 0) {
        spm[q][g]      = rA[0] * inv;
        spm[q][g + 8]  = rB[0] * inv;
        spm[q][g + 16] = rA[1] * inv;
        spm[q][g + 24] = rB[1] * inv;
    }
    if (g == 0) {
#pragma unroll
        for (int nt = 0; nt < 4; nt++) {
            spl[q][nt * 8 + 2 * t]     = cs[nt][0] * inv;
            spl[q][nt * 8 + 2 * t + 1] = cs[nt][1] * inv;
        }
    }
    __syncwarp();

    // z[d] = sum_m pm[m]*d_l[m,d] + pl[m]*e_l[m,d]
    float acc0 = 0.0f, acc1 = 0.0f;
#pragma unroll 8
    for (int m = 0; m < 32; m++) {
        const float pmv = spm[q][m];
        const float plv = spl[q][m];
        acc0 += pmv * sd[m][lane]      + plv * se[m][lane];
        acc1 += pmv * sd[m][lane + 32] + plv * se[m][lane + 32];
    }

    // scatter-store into packed A-fragment layout (tf32-rounded), nks = 96
    {
        const int r      = b * TT + qg;
        const int stripe = r >> 7;
        const int ii     = (r >> 4) & 7;
        const int gg     = r & 15;
        const int gq     = gg & 7;
        const int hir    = gg >> 3;
#pragma unroll
        for (int half = 0; half < 2; half++) {
            const int d  = lane + 32 * half;
            const float v = half ? acc1 : acc0;
            const int c  = h * DH + d;
            const int ks = c >> 3;
            const int cc = c & 7;
            const int tc = cc & 3;
            const int hic = cc >> 2;
            const size_t qi = ((size_t)(stripe * 96 + ks) * 8 + ii) * 32
                            + (gq * 4 + tc);
            g_zp[qi * 4 + (hir + 2 * hic)] = __uint_as_float(f2tf32(v));
        }
    }
}

// ---------------------------------------------------------------------------
extern "C" void kernel_launch(void* const* d_in, const int* in_sizes, int n_in,
                              void* d_out, int out_size)
{
    const float* x  = (const float*)d_in[0];  // (2,2048,768)
    const float* W1 = (const float*)d_in[1];  // (768, 3840)
    const float* b1 = (const float*)d_in[2];  // (3840)
    const float* WO = (const float*)d_in[3];  // (768, 768)
    const float* bO = (const float*)d_in[4];  // (768)
    float* out = (float*)d_out;               // (2,2048,768)

    float *abcde, *xp, *zp, *w1p, *wop;
    cudaGetSymbolAddress((void**)&abcde, g_abcde);
    cudaGetSymbolAddress((void**)&xp,    g_xp);
    cudaGetSymbolAddress((void**)&zp,    g_zp);
    cudaGetSymbolAddress((void**)&w1p,   g_w1p);
    cudaGetSymbolAddress((void**)&wop,   g_wop);

    static bool attr_done = false;
    if (!attr_done) {
        cudaFuncSetAttribute(gemm_frag,
                             cudaFuncAttributeMaxDynamicSharedMemorySize, GSMEM);
        attr_done = true;
    }

    const int M  = BB * TT;          // 4096
    const int N1 = 5 * NH * DH;      // 3840
    const int N2 = DMODEL;           // 768
    const int K  = DMODEL;           // 768
    const int nks = K / 8;           // 96

    pack_a<<<dim3(nks, M / 128), 256>>>(x, xp, K);
    pack_b<<<dim3(nks, N1 / 128), 256>>>(W1, w1p, N1);
    pack_b<<<dim3(nks, N2 / 128), 256>>>(WO, wop, N2);

    // 1) abcde = x @ W1 + b1
    gemm_frag<<<dim3(N1 / 128, M / 128), 256, GSMEM>>>(xp, w1p, b1, abcde, M, N1, K);

    // 2) local trittention -> zp (packed, tf32)
    attn_kernel<<<BB * NH * NWIN, 512>>>();

    // 3) out = z @ WO + bO
    gemm_frag<<<dim3(N2 / 128, M / 128), 256, GSMEM>>>(zp, wop, bO, out, M, N2, K);
}